// round 2
// baseline (speedup 1.0000x reference)
#include <cuda_runtime.h>
#include <cuda_bf16.h>

// Problem shape (fixed by reference setup_inputs)
#define BB 16
#define CC 20
#define HHH 256
#define WWW 256
constexpr int NCH = BB * CC;                       // 320
constexpr int HWC = HHH * WWW;                     // 65536
constexpr long long NTOT = (long long)NCH * HWC;   // 20971520
constexpr int BLOCKS_PER_CH = 4;
constexpr int THREADS = 256;
constexpr int NBLOCKS = NCH * BLOCKS_PER_CH;       // 1280
constexpr int CHUNK = HWC / BLOCKS_PER_CH;         // 16384 elems
constexpr int ITERS = CHUNK / (4 * THREADS);       // 16 float4 per thread

// Per-block partials: [focal, mse, l1, Sp, Spy, Spx, Spr2, mass, Sty, Stx]
// Written (not accumulated) by every block each launch -> no zeroing needed,
// deterministic across graph replays.
__device__ float g_part[NBLOCKS * 10];

// ---------------- packed f32x2 helpers (Blackwell) ----------------
typedef unsigned long long u64;

__device__ __forceinline__ u64 pk(float lo, float hi) {
    u64 r; asm("mov.b64 %0, {%1, %2};" : "=l"(r) : "f"(lo), "f"(hi)); return r;
}
__device__ __forceinline__ void upk(u64 v, float& lo, float& hi) {
    asm("mov.b64 {%0, %1}, %2;" : "=f"(lo), "=f"(hi) : "l"(v));
}
__device__ __forceinline__ u64 fma2(u64 a, u64 b, u64 c) {
    u64 d; asm("fma.rn.f32x2 %0, %1, %2, %3;" : "=l"(d) : "l"(a), "l"(b), "l"(c)); return d;
}
__device__ __forceinline__ u64 add2(u64 a, u64 b) {
    u64 d; asm("add.rn.f32x2 %0, %1, %2;" : "=l"(d) : "l"(a), "l"(b)); return d;
}
__device__ __forceinline__ u64 mul2(u64 a, u64 b) {
    u64 d; asm("mul.rn.f32x2 %0, %1, %2;" : "=l"(d) : "l"(a), "l"(b)); return d;
}
__device__ __forceinline__ float ex2a(float x) { float r; asm("ex2.approx.f32 %0, %1;" : "=f"(r) : "f"(x)); return r; }
__device__ __forceinline__ float lg2a(float x) { float r; asm("lg2.approx.f32 %0, %1;" : "=f"(r) : "f"(x)); return r; }
__device__ __forceinline__ float rcpa(float x) { float r; asm("rcp.approx.f32 %0, %1;" : "=f"(r) : "f"(x)); return r; }

__global__ __launch_bounds__(THREADS) void pass_kernel(
    const float4* __restrict__ pred, const float4* __restrict__ targ)
{
    const int blk = blockIdx.x;
    const int ch  = blk >> 2;
    const int sub = blk & 3;
    const int base4 = (ch * HWC + sub * CHUNK) >> 2;

    const u64 C_one    = pk(1.0f, 1.0f);
    const u64 C_neg1   = pk(-1.0f, -1.0f);
    const u64 C_two    = pk(2.0f, 2.0f);
    const u64 C_neghalf= pk(-0.5f, -0.5f);
    const u64 C_3q     = pk(0.75f, 0.75f);
    const u64 C_eps    = pk(1e-8f, 1e-8f);
    const u64 C_nL2E   = pk(-1.4426950408889634f, -1.4426950408889634f);
    const u64 C_nLN2   = pk(-0.6931471805599453f, -0.6931471805599453f);

    u64 focal2 = 0, mse2 = 0, l12 = 0;
    u64 Sp2 = 0, Spy2 = 0, Spx2 = 0, Spr2_2 = 0;
    u64 mass2 = 0, Sty2 = 0, Stx2 = 0;

#pragma unroll 4
    for (int it = 0; it < ITERS; ++it) {
        const int idx4 = base4 + it * THREADS + threadIdx.x;
        const float4 pr = pred[idx4];
        const float4 tg = targ[idx4];

        const int hw = (idx4 << 2) & (HWC - 1);
        const float y  = (float)(hw >> 8);
        const float x0 = (float)(hw & 255);
        const float yy = y * y;
        const u64 y2b  = pk(y, y);
        const u64 yy2  = pk(yy, yy);

#define PAIR(PLO, PHI, TLO, THI, XOFF)                                        \
        {                                                                     \
            u64 pv2 = pk(PLO, PHI);                                           \
            u64 tv2 = pk(TLO, THI);                                           \
            u64 x2  = pk(x0 + (XOFF), x0 + (XOFF) + 1.0f);                    \
            /* sigmoid: p = 1/(1+exp(-v)) */                                  \
            u64 a2 = mul2(pv2, C_nL2E);                                       \
            float alo, ahi; upk(a2, alo, ahi);                                \
            u64 e2 = pk(ex2a(alo), ex2a(ahi));                                \
            u64 den2 = add2(e2, C_one);                                       \
            float dlo, dhi; upk(den2, dlo, dhi);                              \
            u64 p2 = pk(rcpa(dlo), rcpa(dhi));                                \
            /* focal */                                                       \
            u64 q2  = fma2(p2, C_neg1, C_one);      /* 1-p */                 \
            u64 s2  = fma2(p2, C_two, C_neg1);      /* 2p-1 */                \
            u64 pt2 = fma2(s2, tv2, q2);            /* t?p:1-p */             \
            u64 at2 = fma2(tv2, C_neghalf, C_3q);   /* 0.75-0.5t */           \
            u64 om2 = fma2(pt2, C_neg1, C_one);     /* 1-pt */                \
            u64 pe2 = add2(pt2, C_eps);                                       \
            float llo, lhi; upk(pe2, llo, lhi);                               \
            u64 lg2v = pk(lg2a(llo), lg2a(lhi));                              \
            u64 nl2  = mul2(lg2v, C_nLN2);          /* -log(pt+eps) */        \
            u64 w2   = mul2(at2, om2);                                        \
            w2       = mul2(w2, om2);                                         \
            focal2   = fma2(w2, nl2, focal2);                                 \
            /* sparsity */                                                    \
            u64 d2 = fma2(tv2, C_neg1, pv2);                                  \
            mse2 = fma2(d2, d2, mse2);                                        \
            l12  = add2(l12, pv2 & 0x7fffffff7fffffffULL);  /* |pred| */      \
            /* moments */                                                     \
            Sp2  = add2(Sp2, p2);                                             \
            Spy2 = fma2(p2, y2b, Spy2);                                       \
            Spx2 = fma2(p2, x2, Spx2);                                        \
            u64 rr2 = fma2(x2, x2, yy2);                                      \
            Spr2_2  = fma2(p2, rr2, Spr2_2);                                  \
            mass2 = add2(mass2, tv2);                                         \
            Sty2  = fma2(tv2, y2b, Sty2);                                     \
            Stx2  = fma2(tv2, x2, Stx2);                                      \
        }

        PAIR(pr.x, pr.y, tg.x, tg.y, 0.0f)
        PAIR(pr.z, pr.w, tg.z, tg.w, 2.0f)
#undef PAIR
    }

    // collapse packed halves -> 10 scalars
    float vals[10];
    {
        float lo, hi;
        upk(focal2, lo, hi); vals[0] = lo + hi;
        upk(mse2,   lo, hi); vals[1] = lo + hi;
        upk(l12,    lo, hi); vals[2] = lo + hi;
        upk(Sp2,    lo, hi); vals[3] = lo + hi;
        upk(Spy2,   lo, hi); vals[4] = lo + hi;
        upk(Spx2,   lo, hi); vals[5] = lo + hi;
        upk(Spr2_2, lo, hi); vals[6] = lo + hi;
        upk(mass2,  lo, hi); vals[7] = lo + hi;
        upk(Sty2,   lo, hi); vals[8] = lo + hi;
        upk(Stx2,   lo, hi); vals[9] = lo + hi;
    }

#pragma unroll
    for (int v = 0; v < 10; v++) {
#pragma unroll
        for (int o = 16; o > 0; o >>= 1)
            vals[v] += __shfl_xor_sync(0xffffffffu, vals[v], o);
    }

    __shared__ float sred[THREADS / 32][10];
    const int warp = threadIdx.x >> 5;
    const int lane = threadIdx.x & 31;
    if (lane == 0) {
#pragma unroll
        for (int v = 0; v < 10; v++) sred[warp][v] = vals[v];
    }
    __syncthreads();

    if (threadIdx.x < 10) {
        float s = 0.f;
#pragma unroll
        for (int w = 0; w < THREADS / 32; w++) s += sred[w][threadIdx.x];
        g_part[blk * 10 + threadIdx.x] = s;   // private slot, no atomics
    }
}

__global__ void final_kernel(float* __restrict__ out, int out_size) {
    const int tid = threadIdx.x;  // 512 threads
    float conc = 0.f, nv = 0.f, fo = 0.f, ms = 0.f, l1 = 0.f;

    if (tid < NCH) {
        float s[7] = {0, 0, 0, 0, 0, 0, 0};
#pragma unroll
        for (int sub = 0; sub < BLOCKS_PER_CH; sub++) {
            const float* a = &g_part[(tid * BLOCKS_PER_CH + sub) * 10];
            fo += a[0]; ms += a[1]; l1 += a[2];
#pragma unroll
            for (int v = 0; v < 7; v++) s[v] += a[3 + v];
        }
        const float Sp = s[0], Spy = s[1], Spx = s[2], Spr2 = s[3];
        const float mass = s[4], Sty = s[5], Stx = s[6];
        const bool valid = mass > 0.0f;
        const float safe = valid ? mass : 1.0f;
        const float cy = Sty / safe;
        const float cx = Stx / safe;
        const float ps = (Spr2 - 2.0f * (cy * Spy + cx * Spx)
                          + (cy * cy + cx * cx) * Sp) * (1.0f / (float)HWC);
        if (valid) { conc = ps; nv = 1.0f; }
    }

    float red[5] = {conc, nv, fo, ms, l1};
#pragma unroll
    for (int v = 0; v < 5; v++) {
#pragma unroll
        for (int o = 16; o > 0; o >>= 1)
            red[v] += __shfl_xor_sync(0xffffffffu, red[v], o);
    }
    __shared__ float sr[16][5];
    const int warp = tid >> 5, lane = tid & 31;
    if (lane == 0) {
#pragma unroll
        for (int v = 0; v < 5; v++) sr[warp][v] = red[v];
    }
    __syncthreads();

    if (tid == 0) {
        float tot[5] = {0, 0, 0, 0, 0};
#pragma unroll
        for (int w = 0; w < 16; w++)
#pragma unroll
            for (int v = 0; v < 5; v++) tot[v] += sr[w][v];

        const float inv = 1.0f / (float)NTOT;
        const float focal = tot[2] * inv;
        const float sparsity = tot[3] * inv + tot[4] * inv;  // mse + 1.0*L1
        const float concentration = (tot[1] > 0.f) ? (tot[0] / tot[1]) : 0.0f;
        const float total = 1.0f * focal + 0.8f * sparsity + 1.5f * concentration;

        out[0] = total;
        if (out_size > 1) out[1] = focal;
        if (out_size > 2) out[2] = sparsity;
        if (out_size > 3) out[3] = concentration;
    }
}

extern "C" void kernel_launch(void* const* d_in, const int* in_sizes, int n_in,
                              void* d_out, int out_size) {
    const float4* pred = (const float4*)d_in[0];
    const float4* targ = (const float4*)d_in[1];
    float* out = (float*)d_out;

    pass_kernel<<<NBLOCKS, THREADS>>>(pred, targ);
    final_kernel<<<1, 512>>>(out, out_size);
}

// round 3
// speedup vs baseline: 1.0945x; 1.0945x over previous
#include <cuda_runtime.h>
#include <cuda_bf16.h>

// Problem shape (fixed by reference setup_inputs)
#define BB 16
#define CC 20
#define HHH 256
#define WWW 256
constexpr int NCH = BB * CC;                       // 320
constexpr int HWC = HHH * WWW;                     // 65536
constexpr long long NTOT = (long long)NCH * HWC;   // 20971520
constexpr int BLOCKS_PER_CH = 4;
constexpr int THREADS = 256;
constexpr int NBLOCKS = NCH * BLOCKS_PER_CH;       // 1280
constexpr int CHUNK = HWC / BLOCKS_PER_CH;         // 16384 elems
constexpr int ITERS = CHUNK / (4 * THREADS);       // 16 float4 per thread

// Per-block partials: [focal, mse, l1, Sp, Spy, Spx, Spr2, mass, Sty, Stx]
// Overwritten by every block each launch -> no zeroing needed, deterministic
// across graph replays.
__device__ float g_part[NBLOCKS * 10];
__device__ unsigned int g_count;   // zero-initialized once; reset to 0 by the
                                   // finalizing block every launch.

__global__ __launch_bounds__(THREADS) void fused_kernel(
    const float4* __restrict__ pred, const float4* __restrict__ targ,
    float* __restrict__ out, int out_size)
{
    const int blk = blockIdx.x;
    const int ch  = blk >> 2;
    const int sub = blk & 3;
    const int base4 = (ch * HWC + sub * CHUNK) >> 2;

    float focal = 0.f, mse = 0.f, l1 = 0.f;
    float Sp = 0.f, Spy = 0.f, Spx = 0.f, Spr2 = 0.f;
    float mass = 0.f, Sty = 0.f, Stx = 0.f;

#pragma unroll
    for (int it = 0; it < ITERS; ++it) {
        const int idx4 = base4 + it * THREADS + threadIdx.x;
        const float4 pr = __ldcs(&pred[idx4]);   // streaming: read-once data
        const float4 tg = __ldcs(&targ[idx4]);

        const int hw = (idx4 << 2) & (HWC - 1);
        const float y  = (float)(hw >> 8);
        const float x0 = (float)(hw & 255);
        const float yy = y * y;

#define LANE(PV, TV, XO)                                                    \
        {                                                                   \
            float pv = (PV), tv = (TV);                                     \
            float x  = x0 + (XO);                                           \
            float p  = __fdividef(1.0f, 1.0f + __expf(-pv));                \
            /* pt = t ? p : 1-p  (t is exactly 0 or 1) */                   \
            float pt = fmaf(2.0f * p - 1.0f, tv, 1.0f - p);                 \
            float at = 0.75f - 0.5f * tv;                                   \
            float omp = 1.0f - pt;                                          \
            focal = fmaf(at * omp * omp, -__logf(pt + 1e-8f), focal);       \
            float d = pv - tv;                                              \
            mse = fmaf(d, d, mse);                                          \
            l1 += fabsf(pv);                                                \
            Sp  += p;                                                       \
            Spy = fmaf(p, y, Spy);                                          \
            Spx = fmaf(p, x, Spx);                                          \
            Spr2 = fmaf(p, fmaf(x, x, yy), Spr2);                           \
            mass += tv;                                                     \
            Sty = fmaf(tv, y, Sty);                                         \
            Stx = fmaf(tv, x, Stx);                                         \
        }

        LANE(pr.x, tg.x, 0.0f)
        LANE(pr.y, tg.y, 1.0f)
        LANE(pr.z, tg.z, 2.0f)
        LANE(pr.w, tg.w, 3.0f)
#undef LANE
    }

    // ---- block reduction of 10 values ----
    float vals[10] = {focal, mse, l1, Sp, Spy, Spx, Spr2, mass, Sty, Stx};
#pragma unroll
    for (int v = 0; v < 10; v++) {
#pragma unroll
        for (int o = 16; o > 0; o >>= 1)
            vals[v] += __shfl_xor_sync(0xffffffffu, vals[v], o);
    }

    __shared__ float sred[THREADS / 32][10];
    const int warp = threadIdx.x >> 5;
    const int lane = threadIdx.x & 31;
    if (lane == 0) {
#pragma unroll
        for (int v = 0; v < 10; v++) sred[warp][v] = vals[v];
    }
    __syncthreads();

    if (threadIdx.x < 10) {
        float s = 0.f;
#pragma unroll
        for (int w = 0; w < THREADS / 32; w++) s += sred[w][threadIdx.x];
        g_part[blk * 10 + threadIdx.x] = s;   // private slot, no atomics
    }

    // ---- last-block-done finalize (fused; no extra launch) ----
    __shared__ bool s_last;
    __threadfence();
    if (threadIdx.x == 0) {
        const unsigned int prev = atomicAdd(&g_count, 1u);
        s_last = (prev == (unsigned int)(NBLOCKS - 1));
    }
    __syncthreads();
    if (!s_last) return;
    __threadfence();   // acquire: all partials visible

    const int tid = threadIdx.x;
    float conc = 0.f, nv = 0.f, fo = 0.f, ms = 0.f, la = 0.f;

    // 320 channels over 256 threads: tid handles ch=tid and (tid<64) ch=tid+256
#pragma unroll
    for (int rep = 0; rep < 2; rep++) {
        const int c = tid + rep * THREADS;
        if (c < NCH) {
            float s[7] = {0, 0, 0, 0, 0, 0, 0};
#pragma unroll
            for (int sb = 0; sb < BLOCKS_PER_CH; sb++) {
                const float* a = &g_part[(c * BLOCKS_PER_CH + sb) * 10];
                fo += a[0]; ms += a[1]; la += a[2];
#pragma unroll
                for (int v = 0; v < 7; v++) s[v] += a[3 + v];
            }
            const float SSp = s[0], SSpy = s[1], SSpx = s[2], SSpr2 = s[3];
            const float smass = s[4], SSty = s[5], SStx = s[6];
            const bool valid = smass > 0.0f;
            const float safe = valid ? smass : 1.0f;
            const float cy = SSty / safe;
            const float cx = SStx / safe;
            const float ps = (SSpr2 - 2.0f * (cy * SSpy + cx * SSpx)
                              + (cy * cy + cx * cx) * SSp) * (1.0f / (float)HWC);
            if (valid) { conc += ps; nv += 1.0f; }
        }
    }

    float red[5] = {conc, nv, fo, ms, la};
#pragma unroll
    for (int v = 0; v < 5; v++) {
#pragma unroll
        for (int o = 16; o > 0; o >>= 1)
            red[v] += __shfl_xor_sync(0xffffffffu, red[v], o);
    }
    __shared__ float sr[THREADS / 32][5];
    if (lane == 0) {
#pragma unroll
        for (int v = 0; v < 5; v++) sr[warp][v] = red[v];
    }
    __syncthreads();

    if (tid == 0) {
        float tot[5] = {0, 0, 0, 0, 0};
#pragma unroll
        for (int w = 0; w < THREADS / 32; w++)
#pragma unroll
            for (int v = 0; v < 5; v++) tot[v] += sr[w][v];

        const float inv = 1.0f / (float)NTOT;
        const float focal_m = tot[2] * inv;
        const float sparsity = tot[3] * inv + tot[4] * inv;  // mse + 1.0*L1
        const float concentration = (tot[1] > 0.f) ? (tot[0] / tot[1]) : 0.0f;
        const float total = 1.0f * focal_m + 0.8f * sparsity + 1.5f * concentration;

        out[0] = total;
        if (out_size > 1) out[1] = focal_m;
        if (out_size > 2) out[2] = sparsity;
        if (out_size > 3) out[3] = concentration;

        g_count = 0;          // reset for next graph replay (deterministic)
        __threadfence();
    }
}

extern "C" void kernel_launch(void* const* d_in, const int* in_sizes, int n_in,
                              void* d_out, int out_size) {
    const float4* pred = (const float4*)d_in[0];
    const float4* targ = (const float4*)d_in[1];
    float* out = (float*)d_out;

    fused_kernel<<<NBLOCKS, THREADS>>>(pred, targ, out, out_size);
}